// round 8
// baseline (speedup 1.0000x reference)
#include <cuda_runtime.h>
#include <cuda_fp16.h>
#include <cstdint>
#include <cstddef>

// ---------------- problem constants ----------------
#define BATCH   16
#define NSIZE   512
#define FRAMES  2049                  // T+1 output frames
#define XLEN    (NSIZE * 2048)        // samples per batch = 1048576
#define KF      512                   // folded K (1024 -> 512 via MDCT symmetry)

// ---------------- GEMM tiling ----------------
#define MT      128                   // channel tile
#define NTL     128                   // frame tile
#define KC      64                    // K chunk (64 fp16 = 128B = SW128 atom)
#define NCH     (KF / KC)             // 8 chunks
#define STAGES  4
#define TILE_BYTES  (128 * 64 * 2)    // 16 KB per operand tile
#define STAGE_BYTES (3 * TILE_BYTES)  // Ah, Al, B = 48 KB
#define SMEM_TOTAL  (STAGES * STAGE_BYTES)  // 192 KB

// ---------------- scratch (device globals: allocation-free) ----------------
static __device__ __align__(16) __half g_u [(size_t)BATCH * FRAMES * KF];  // 33.6 MB
static __device__ __align__(16) __half g_gh[NSIZE * KF];                    // folded filter hi
static __device__ __align__(16) __half g_gl[NSIZE * KF];                    // folded filter lo

// ---------------- PTX helpers ----------------
__device__ __forceinline__ uint32_t smem_u32(const void* p) {
    uint32_t a;
    asm("{ .reg .u64 t; cvta.to.shared.u64 t, %1; cvt.u32.u64 %0, t; }" : "=r"(a) : "l"(p));
    return a;
}

__device__ __forceinline__ void cpa16(uint32_t dst, const void* src, int src_size) {
    asm volatile("cp.async.cg.shared.global [%0], [%1], 16, %2;"
                 :: "r"(dst), "l"(src), "r"(src_size) : "memory");
}

#define CP_COMMIT() asm volatile("cp.async.commit_group;" ::: "memory")
#define CP_WAIT2()  asm volatile("cp.async.wait_group 2;" ::: "memory")

#define LDSM4(r0, r1, r2, r3, ad)                                              \
    asm volatile("ldmatrix.sync.aligned.m8n8.x4.shared.b16 {%0,%1,%2,%3}, [%4];" \
                 : "=r"(r0), "=r"(r1), "=r"(r2), "=r"(r3) : "r"(ad))

#define MMA16816(cr, a0, a1, a2, a3, b0, b1)                                   \
    asm volatile("mma.sync.aligned.m16n8k16.row.col.f32.f16.f16.f32 "          \
                 "{%0,%1,%2,%3}, {%4,%5,%6,%7}, {%8,%9}, {%0,%1,%2,%3};"       \
                 : "+f"((cr)[0]), "+f"((cr)[1]), "+f"((cr)[2]), "+f"((cr)[3])  \
                 : "r"(a0), "r"(a1), "r"(a2), "r"(a3), "r"(b0), "r"(b1))

__device__ __forceinline__ uint32_t swz(uint32_t off) {
    return off ^ ((off >> 3) & 0x70);
}

// ---------------- prepass 1: fold + split filter ----------------
// g[k,n] = f[k, n<256 ? n : n+256];  gh = fp16(g); gl = fp16(g - gh)
__global__ void __launch_bounds__(256) mdct_wsplit(const float* __restrict__ w) {
    int i = blockIdx.x * 256 + threadIdx.x;      // < 512*512
    int k = i >> 9, n = i & 511;
    int t = n + ((n >> 8) << 8);                  // n<256: n ; n>=256: n+256
    float g = w[k * 1024 + t];
    __half gh = __float2half_rn(g);
    __half gl = __float2half_rn(g - __half2float(gh));
    g_gh[i] = gh;
    g_gl[i] = gl;
}

// ---------------- prepass 2: fold input frames (exact fp32) -> fp16 ----------------
// frame f window x_w[t] = x[b, (f-1)*512 + t] (zero outside [0, XLEN))
//   n in [0,256):   u[n] = x_w[n]     - x_w[511-n]
//   n in [256,512): u[n] = x_w[n+256] + x_w[1279-n]
__global__ void __launch_bounds__(128) mdct_fold(const float* __restrict__ x) {
    int f = blockIdx.x;                 // 0..2048
    int b = blockIdx.y;
    int tid = threadIdx.x;              // 0..127, 4 n's each
    const float* xb = x + (size_t)b * XLEN;
    long s0 = (long)(f - 1) * NSIZE;
    int n4 = tid * 4;

    float u0, u1, u2, u3;
    if (tid < 64) {                     // first half: n in [0,256)
        if (f == 0) {
            u0 = u1 = u2 = u3 = 0.f;
        } else {
            float4 a = *(const float4*)(xb + s0 + n4);
            float4 r = *(const float4*)(xb + s0 + 508 - n4);
            u0 = a.x - r.w; u1 = a.y - r.z; u2 = a.z - r.y; u3 = a.w - r.x;
        }
    } else {                            // second half: n in [256,512)
        if (f == 2048) {
            u0 = u1 = u2 = u3 = 0.f;
        } else {
            float4 a = *(const float4*)(xb + s0 + n4 + 256);
            float4 r = *(const float4*)(xb + s0 + 1276 - n4);
            u0 = a.x + r.w; u1 = a.y + r.z; u2 = a.z + r.y; u3 = a.w + r.x;
        }
    }
    __half2 h01 = __floats2half2_rn(u0, u1);
    __half2 h23 = __floats2half2_rn(u2, u3);
    uint2 v;
    v.x = *(uint32_t*)&h01;
    v.y = *(uint32_t*)&h23;
    *(uint2*)(g_u + ((size_t)(b * FRAMES + f)) * KF + n4) = v;
}

// ---------------- main GEMM: out[b,k,f] = sum_n (gh+gl)[k,n] * u[b,f,n] ----------------
__device__ __forceinline__ void load_stage(uint32_t sb, int stage, int kc,
                                           int m0, int f0, int b, int tid) {
    uint32_t base = sb + stage * STAGE_BYTES;
    int c = tid & 7;                    // 16B column
    int r0 = tid >> 3;                  // base row
    int kcol = kc * KC + c * 8;
#pragma unroll
    for (int i = 0; i < 4; i++) {
        int row = r0 + i * 32;
        uint32_t sw = swz((row << 7) | (c << 4));
        const __half* pa = g_gh + (m0 + row) * KF + kcol;
        const __half* pl = g_gl + (m0 + row) * KF + kcol;
        cpa16(base + sw, pa, 16);
        cpa16(base + TILE_BYTES + sw, pl, 16);
        int f = f0 + row;
        int valid = (f <= 2048) ? 16 : 0;
        size_t fr = (f <= 2048) ? (size_t)(b * FRAMES + f) : 0;
        cpa16(base + 2 * TILE_BYTES + sw, g_u + fr * KF + kcol, valid);
    }
}

extern "C" __global__ void __launch_bounds__(256, 1) mdct_gemm(float* __restrict__ out) {
    extern __shared__ char smem[];
    const uint32_t sb = smem_u32(smem);
    const int tid = threadIdx.x;
    const int lane = tid & 31;
    const int wid = tid >> 5;
    const int wm = wid & 1;             // warp M index (2)
    const int wn = wid >> 1;            // warp N index (4)

    const int m0 = blockIdx.x * MT;     // channel tile
    const int f0 = blockIdx.y * NTL;    // frame tile
    const int b  = blockIdx.z;

    // ldmatrix lane addressing (row within 16-row tile, 16B column half)
    const int rowSel = (((lane >> 3) & 1) << 3) | (lane & 7);
    const int colSel = (lane >> 4) << 4;

    float C[4][4][4];
#pragma unroll
    for (int mt = 0; mt < 4; mt++)
#pragma unroll
        for (int nt = 0; nt < 4; nt++)
#pragma unroll
            for (int j = 0; j < 4; j++) C[mt][nt][j] = 0.f;

    // prologue: stages 0..2
#pragma unroll
    for (int s = 0; s < STAGES - 1; s++) {
        load_stage(sb, s, s, m0, f0, b, tid);
        CP_COMMIT();
    }

    for (int kc = 0; kc < NCH; kc++) {
        CP_WAIT2();
        __syncthreads();

        if (kc + STAGES - 1 < NCH)
            load_stage(sb, (kc + STAGES - 1) & (STAGES - 1), kc + STAGES - 1, m0, f0, b, tid);
        CP_COMMIT();

        const uint32_t aH = sb + (kc & (STAGES - 1)) * STAGE_BYTES;
        const uint32_t aL = aH + TILE_BYTES;
        const uint32_t bB = aH + 2 * TILE_BYTES;

#pragma unroll
        for (int s = 0; s < 4; s++) {
            const int kb = s * 32 + colSel;

            // B fragments: 4 n-tiles x {k0-7, k8-15}, shared by both filter passes
            uint32_t bf[4][2];
#pragma unroll
            for (int nb = 0; nb < 2; nb++) {
                uint32_t off = (uint32_t)((wn * 32 + nb * 16 + rowSel) << 7) | kb;
                uint32_t ad = bB + swz(off);
                uint32_t r0, r1, r2, r3;
                LDSM4(r0, r1, r2, r3, ad);
                bf[nb * 2][0] = r0; bf[nb * 2][1] = r2;
                bf[nb * 2 + 1][0] = r1; bf[nb * 2 + 1][1] = r3;
            }

#pragma unroll
            for (int p = 0; p < 2; p++) {
                const uint32_t ab = p ? aL : aH;
#pragma unroll
                for (int mt = 0; mt < 4; mt++) {
                    uint32_t off = (uint32_t)((wm * 64 + mt * 16 + rowSel) << 7) | kb;
                    uint32_t ad = ab + swz(off);
                    uint32_t a0, a1, a2, a3;
                    LDSM4(a0, a1, a2, a3, ad);
#pragma unroll
                    for (int nt = 0; nt < 4; nt++)
                        MMA16816(C[mt][nt], a0, a1, a2, a3, bf[nt][0], bf[nt][1]);
                }
            }
        }
        __syncthreads();
    }

    // ---- epilogue: C frags -> gmem (out[b, k, f], f-major, FRAMES=2049) ----
    const int rbase = m0 + wm * 64 + (lane >> 2);
    const int cbase = f0 + wn * 32 + (lane & 3) * 2;
#pragma unroll
    for (int mt = 0; mt < 4; mt++) {
#pragma unroll
        for (int nt = 0; nt < 4; nt++) {
            int r = rbase + mt * 16;
            int c = cbase + nt * 8;
            float* p0 = out + ((size_t)(b * NSIZE + r)) * FRAMES;
            float* p1 = p0 + 8 * FRAMES;          // row r+8
            if (c < FRAMES)     p0[c]     = C[mt][nt][0];
            if (c + 1 < FRAMES) p0[c + 1] = C[mt][nt][1];
            if (c < FRAMES)     p1[c]     = C[mt][nt][2];
            if (c + 1 < FRAMES) p1[c + 1] = C[mt][nt][3];
        }
    }
}

// ---------------- launch ----------------
extern "C" void kernel_launch(void* const* d_in, const int* in_sizes, int n_in,
                              void* d_out, int out_size) {
    (void)in_sizes; (void)n_in; (void)out_size;
    const float* x = (const float*)d_in[0];       // [16, 1, 1048576] fp32
    const float* w = (const float*)d_in[1];       // [512, 1, 1024] fp32
    float* out = (float*)d_out;                   // [16, 512, 2049] fp32

    cudaFuncSetAttribute(mdct_gemm, cudaFuncAttributeMaxDynamicSharedMemorySize, SMEM_TOTAL);

    mdct_wsplit<<<(NSIZE * KF) / 256, 256>>>(w);
    mdct_fold<<<dim3(FRAMES, BATCH), 128>>>(x);

    dim3 grid(NSIZE / MT, (FRAMES + NTL - 1) / NTL, BATCH);   // (4, 17, 16)
    mdct_gemm<<<grid, 256, SMEM_TOTAL>>>(out);
}

// round 11
// speedup vs baseline: 1.4637x; 1.4637x over previous
#include <cuda_runtime.h>
#include <cuda_fp16.h>
#include <cstdint>
#include <cstddef>

// ---------------- problem constants ----------------
#define BATCH   16
#define NSIZE   512
#define FRAMES  2049                  // T+1 output frames
#define XLEN    (NSIZE * 2048)        // samples per batch = 1048576
#define KF      512                   // folded K (1024 -> 512 via MDCT symmetry)

// ---------------- GEMM tiling ----------------
#define MT      128                   // channel tile
#define NTL     256                   // frame tile
#define KC      64                    // K chunk (64 fp16 = 128B = SW128 atom)
#define NCH     (KF / KC)             // 8 chunks
#define STAGES  4
#define A_BYTES (MT * KC * 2)         // 16 KB
#define B_BYTES (NTL * KC * 2)        // 32 KB
#define STAGE_BYTES (A_BYTES + B_BYTES)     // 48 KB
#define SMEM_TOTAL  (STAGES * STAGE_BYTES)  // 192 KB

// ---------------- scratch (device globals: allocation-free) ----------------
static __device__ __align__(16) __half g_u [(size_t)BATCH * FRAMES * KF];  // 33.6 MB
static __device__ __align__(16) __half g_gh[NSIZE * KF];                    // folded filter (fp16)

// ---------------- PTX helpers ----------------
__device__ __forceinline__ uint32_t smem_u32(const void* p) {
    uint32_t a;
    asm("{ .reg .u64 t; cvta.to.shared.u64 t, %1; cvt.u32.u64 %0, t; }" : "=r"(a) : "l"(p));
    return a;
}

__device__ __forceinline__ void cpa16(uint32_t dst, const void* src, int src_size) {
    asm volatile("cp.async.cg.shared.global [%0], [%1], 16, %2;"
                 :: "r"(dst), "l"(src), "r"(src_size) : "memory");
}

#define CP_COMMIT() asm volatile("cp.async.commit_group;" ::: "memory")
#define CP_WAIT2()  asm volatile("cp.async.wait_group 2;" ::: "memory")

#define LDSM4(r0, r1, r2, r3, ad)                                              \
    asm volatile("ldmatrix.sync.aligned.m8n8.x4.shared.b16 {%0,%1,%2,%3}, [%4];" \
                 : "=r"(r0), "=r"(r1), "=r"(r2), "=r"(r3) : "r"(ad))

#define MMA16816(cr, a0, a1, a2, a3, b0, b1)                                   \
    asm volatile("mma.sync.aligned.m16n8k16.row.col.f32.f16.f16.f32 "          \
                 "{%0,%1,%2,%3}, {%4,%5,%6,%7}, {%8,%9}, {%0,%1,%2,%3};"       \
                 : "+f"((cr)[0]), "+f"((cr)[1]), "+f"((cr)[2]), "+f"((cr)[3])  \
                 : "r"(a0), "r"(a1), "r"(a2), "r"(a3), "r"(b0), "r"(b1))

__device__ __forceinline__ uint32_t swz(uint32_t off) {
    return off ^ ((off >> 3) & 0x70);
}

// ---------------- prepass 1: fold filter -> fp16 ----------------
// g[k,n] = f[k, n<256 ? n : n+256]
__global__ void __launch_bounds__(256) mdct_wfold(const float* __restrict__ w) {
    int i = blockIdx.x * 256 + threadIdx.x;      // < 512*512
    int k = i >> 9, n = i & 511;
    int t = n + ((n >> 8) << 8);                  // n<256: n ; n>=256: n+256
    g_gh[i] = __float2half_rn(w[k * 1024 + t]);
}

// ---------------- prepass 2: fold input frames (exact fp32) -> fp16 ----------------
// frame f window x_w[t] = x[b, (f-1)*512 + t] (zero outside [0, XLEN))
//   n in [0,256):   u[n] = x_w[n]     - x_w[511-n]
//   n in [256,512): u[n] = x_w[n+256] + x_w[1279-n]
__global__ void __launch_bounds__(128) mdct_fold(const float* __restrict__ x) {
    int f = blockIdx.x;                 // 0..2048
    int b = blockIdx.y;
    int tid = threadIdx.x;              // 0..127, 4 n's each
    const float* xb = x + (size_t)b * XLEN;
    long s0 = (long)(f - 1) * NSIZE;
    int n4 = tid * 4;

    float u0, u1, u2, u3;
    if (tid < 64) {                     // first half: n in [0,256)
        if (f == 0) {
            u0 = u1 = u2 = u3 = 0.f;
        } else {
            float4 a = *(const float4*)(xb + s0 + n4);
            float4 r = *(const float4*)(xb + s0 + 508 - n4);
            u0 = a.x - r.w; u1 = a.y - r.z; u2 = a.z - r.y; u3 = a.w - r.x;
        }
    } else {                            // second half: n in [256,512)
        if (f == 2048) {
            u0 = u1 = u2 = u3 = 0.f;
        } else {
            float4 a = *(const float4*)(xb + s0 + n4 + 256);
            float4 r = *(const float4*)(xb + s0 + 1276 - n4);
            u0 = a.x + r.w; u1 = a.y + r.z; u2 = a.z + r.y; u3 = a.w + r.x;
        }
    }
    __half2 h01 = __floats2half2_rn(u0, u1);
    __half2 h23 = __floats2half2_rn(u2, u3);
    uint2 v;
    v.x = *(uint32_t*)&h01;
    v.y = *(uint32_t*)&h23;
    *(uint2*)(g_u + ((size_t)(b * FRAMES + f)) * KF + n4) = v;
}

// ---------------- main GEMM: out[b,k,f] = sum_n g[k,n] * u[b,f,n] ----------------
__device__ __forceinline__ void load_stage(uint32_t sb, int stage, int kc,
                                           int m0, int f0, int b, int tid) {
    uint32_t base = sb + stage * STAGE_BYTES;
    int c = tid & 7;                    // 16B column
    int r0 = tid >> 3;                  // base row (0..31)
    int kcol = kc * KC + c * 8;
    // A (filter): 128 rows x 8 segs = 1024 -> 4 per thread
#pragma unroll
    for (int i = 0; i < 4; i++) {
        int row = r0 + i * 32;
        uint32_t sw = swz((row << 7) | (c << 4));
        cpa16(base + sw, g_gh + (m0 + row) * KF + kcol, 16);
    }
    // B (folded frames): 256 rows x 8 segs = 2048 -> 8 per thread
#pragma unroll
    for (int i = 0; i < 8; i++) {
        int row = r0 + i * 32;
        uint32_t sw = swz((row << 7) | (c << 4));
        int f = f0 + row;
        int valid = (f <= 2048) ? 16 : 0;
        size_t fr = (f <= 2048) ? (size_t)(b * FRAMES + f) : 0;
        cpa16(base + A_BYTES + sw, g_u + fr * KF + kcol, valid);
    }
}

extern "C" __global__ void __launch_bounds__(256, 1) mdct_gemm(float* __restrict__ out) {
    extern __shared__ char smem[];
    const uint32_t sb = smem_u32(smem);
    const int tid = threadIdx.x;
    const int lane = tid & 31;
    const int wid = tid >> 5;
    const int wm = wid & 1;             // warp M index (2): 64 rows each
    const int wn = wid >> 1;            // warp N index (4): 64 cols each

    const int m0 = blockIdx.x * MT;     // channel tile
    const int f0 = blockIdx.y * NTL;    // frame tile
    const int b  = blockIdx.z;

    // ldmatrix lane addressing (row within 16-row tile, 16B column half)
    const int rowSel = (((lane >> 3) & 1) << 3) | (lane & 7);
    const int colSel = (lane >> 4) << 4;

    float C[4][8][4];
#pragma unroll
    for (int mt = 0; mt < 4; mt++)
#pragma unroll
        for (int nt = 0; nt < 8; nt++)
#pragma unroll
            for (int j = 0; j < 4; j++) C[mt][nt][j] = 0.f;

    // prologue: stages 0..2
#pragma unroll
    for (int s = 0; s < STAGES - 1; s++) {
        load_stage(sb, s, s, m0, f0, b, tid);
        CP_COMMIT();
    }

    for (int kc = 0; kc < NCH; kc++) {
        CP_WAIT2();
        __syncthreads();

        if (kc + STAGES - 1 < NCH)
            load_stage(sb, (kc + STAGES - 1) & (STAGES - 1), kc + STAGES - 1, m0, f0, b, tid);
        CP_COMMIT();

        const uint32_t aB = sb + (kc & (STAGES - 1)) * STAGE_BYTES;
        const uint32_t bB = aB + A_BYTES;

#pragma unroll
        for (int s = 0; s < 4; s++) {
            const int kb = s * 32 + colSel;

            // B fragments: 8 n8-tiles (64 cols) x {k0-7, k8-15}
            uint32_t bf[8][2];
#pragma unroll
            for (int nb = 0; nb < 4; nb++) {
                uint32_t off = (uint32_t)((wn * 64 + nb * 16 + rowSel) << 7) | kb;
                uint32_t ad = bB + swz(off);
                uint32_t r0, r1, r2, r3;
                LDSM4(r0, r1, r2, r3, ad);
                bf[nb * 2][0] = r0; bf[nb * 2][1] = r2;
                bf[nb * 2 + 1][0] = r1; bf[nb * 2 + 1][1] = r3;
            }

#pragma unroll
            for (int mt = 0; mt < 4; mt++) {
                uint32_t off = (uint32_t)((wm * 64 + mt * 16 + rowSel) << 7) | kb;
                uint32_t ad = aB + swz(off);
                uint32_t a0, a1, a2, a3;
                LDSM4(a0, a1, a2, a3, ad);
#pragma unroll
                for (int nt = 0; nt < 8; nt++)
                    MMA16816(C[mt][nt], a0, a1, a2, a3, bf[nt][0], bf[nt][1]);
            }
        }
        __syncthreads();
    }

    // ---- epilogue: C frags -> gmem (out[b, k, f], f-major, FRAMES=2049) ----
    const int rbase = m0 + wm * 64 + (lane >> 2);
    const int cbase = f0 + wn * 64 + (lane & 3) * 2;
#pragma unroll
    for (int mt = 0; mt < 4; mt++) {
#pragma unroll
        for (int nt = 0; nt < 8; nt++) {
            int r = rbase + mt * 16;
            int c = cbase + nt * 8;
            float* p0 = out + ((size_t)(b * NSIZE + r)) * FRAMES;
            float* p1 = p0 + 8 * FRAMES;          // row r+8
            if (c < FRAMES) {
                p0[c] = C[mt][nt][0];
                p1[c] = C[mt][nt][2];
                if (c + 1 < FRAMES) {
                    p0[c + 1] = C[mt][nt][1];
                    p1[c + 1] = C[mt][nt][3];
                }
            }
        }
    }
}

// ---------------- launch ----------------
extern "C" void kernel_launch(void* const* d_in, const int* in_sizes, int n_in,
                              void* d_out, int out_size) {
    (void)in_sizes; (void)n_in; (void)out_size;
    const float* x = (const float*)d_in[0];       // [16, 1, 1048576] fp32
    const float* w = (const float*)d_in[1];       // [512, 1, 1024] fp32
    float* out = (float*)d_out;                   // [16, 512, 2049] fp32

    cudaFuncSetAttribute(mdct_gemm, cudaFuncAttributeMaxDynamicSharedMemorySize, SMEM_TOTAL);

    mdct_wfold<<<(NSIZE * KF) / 256, 256>>>(w);
    mdct_fold<<<dim3(FRAMES, BATCH), 128>>>(x);

    dim3 grid(NSIZE / MT, (FRAMES + NTL - 1) / NTL, BATCH);   // (4, 9, 16)
    mdct_gemm<<<grid, 256, SMEM_TOTAL>>>(out);
}